// round 8
// baseline (speedup 1.0000x reference)
#include <cuda_runtime.h>
#include <cuda_bf16.h>
#include <cstdint>

#define C_DIM 1024
#define NH 16
#define HD 64
#define MAX_T 8192
#define LMAX 1024
#define EPS_RMS 1.1920929e-07f

typedef __nv_bfloat16 bf16;

// ---------------- scratch (device globals; allocation-free rule) ----------
// linear layouts (attention operands)
__device__ bf16 g_qh[MAX_T * C_DIM];
__device__ bf16 g_ql[MAX_T * C_DIM];
__device__ bf16 g_kh2[MAX_T * C_DIM];
__device__ bf16 g_kl2[MAX_T * C_DIM];
__device__ bf16 g_vh2[MAX_T * C_DIM];
__device__ bf16 g_vl2[MAX_T * C_DIM];

// tiled layouts (GEMM operands): [blk128][kblk32][128 rows x 40 elems]
#define TROW 40
#define TBLK_ELEMS (128 * TROW)       // 5120 elems
#define TBLK_BYTES (TBLK_ELEMS * 2)   // 10240 B
#define NKB (C_DIM / 32)              // 32 k-blocks
__device__ bf16 g_xh[(MAX_T / 128) * NKB * TBLK_ELEMS];
__device__ bf16 g_xl[(MAX_T / 128) * NKB * TBLK_ELEMS];
__device__ bf16 g_ath[(MAX_T / 128) * NKB * TBLK_ELEMS];
__device__ bf16 g_atl[(MAX_T / 128) * NKB * TBLK_ELEMS];
__device__ bf16 g_wqh[8 * NKB * TBLK_ELEMS];
__device__ bf16 g_wql[8 * NKB * TBLK_ELEMS];
__device__ bf16 g_wkh[8 * NKB * TBLK_ELEMS];
__device__ bf16 g_wkl[8 * NKB * TBLK_ELEMS];
__device__ bf16 g_wvh[8 * NKB * TBLK_ELEMS];
__device__ bf16 g_wvl[8 * NKB * TBLK_ELEMS];
__device__ bf16 g_woh[8 * NKB * TBLK_ELEMS];
__device__ bf16 g_wol[8 * NKB * TBLK_ELEMS];

// ---------------- helpers ---------------------------------------------
__device__ __forceinline__ uint32_t smem_u32(const void* p) {
    uint32_t a;
    asm("{ .reg .u64 t; cvta.to.shared.u64 t, %1; cvt.u32.u64 %0, t; }"
        : "=r"(a) : "l"(p));
    return a;
}

__device__ __forceinline__ size_t tiled_off(int r, int c) {
    return ((size_t)((r >> 7) * NKB + (c >> 5))) * TBLK_ELEMS +
           (size_t)((r & 127) * TROW + (c & 31));
}

#define LDSM_X4(r0, r1, r2, r3, addr) \
    asm volatile("ldmatrix.sync.aligned.m8n8.x4.shared.b16 {%0,%1,%2,%3}, [%4];" \
                 : "=r"(r0), "=r"(r1), "=r"(r2), "=r"(r3) : "r"(addr))

#define LDSM_X4_T(r0, r1, r2, r3, addr) \
    asm volatile("ldmatrix.sync.aligned.m8n8.x4.trans.shared.b16 {%0,%1,%2,%3}, [%4];" \
                 : "=r"(r0), "=r"(r1), "=r"(r2), "=r"(r3) : "r"(addr))

#define MMA16816(d, a, b) \
    asm volatile("mma.sync.aligned.m16n8k16.row.col.f32.bf16.bf16.f32 " \
                 "{%0,%1,%2,%3}, {%4,%5,%6,%7}, {%8,%9}, {%0,%1,%2,%3};" \
                 : "+f"((d)[0]), "+f"((d)[1]), "+f"((d)[2]), "+f"((d)[3]) \
                 : "r"((a)[0]), "r"((a)[1]), "r"((a)[2]), "r"((a)[3]), \
                   "r"((b)[0]), "r"((b)[1]))

#define CP_ASYNC16(dst, src) \
    asm volatile("cp.async.cg.shared.global [%0], [%1], 16;" :: "r"(dst), "l"(src))
#define CP_COMMIT() asm volatile("cp.async.commit_group;" ::: "memory")
#define CP_WAIT(n)  asm volatile("cp.async.wait_group %0;" :: "n"(n) : "memory")

#define MBAR_INIT(a, cnt) \
    asm volatile("mbarrier.init.shared.b64 [%0], %1;" :: "r"(a), "r"(cnt) : "memory")
#define MBAR_EXPECT_TX(a, bytes) \
    asm volatile("mbarrier.arrive.expect_tx.shared.b64 _, [%0], %1;" \
                 :: "r"(a), "r"(bytes) : "memory")
#define BULK_G2S(dst, src, bytes, mbar) \
    asm volatile("cp.async.bulk.shared::cta.global.mbarrier::complete_tx::bytes " \
                 "[%0], [%1], %2, [%3];" \
                 :: "r"(dst), "l"(src), "r"(bytes), "r"(mbar) : "memory")

__device__ __forceinline__ void mbar_wait(uint32_t a, int phase) {
    asm volatile(
        "{ .reg .pred P;\n"
        "WL%=:\n"
        " mbarrier.try_wait.parity.acquire.cta.shared::cta.b64 P, [%0], %1, 0x989680;\n"
        " @P bra WD%=;\n"
        " bra WL%=;\n"
        "WD%=: }"
        :: "r"(a), "r"(phase) : "memory");
}

__device__ __forceinline__ void split2(float x, float y, uint32_t& h, uint32_t& l) {
    bf16 hx = __float2bfloat16(x);
    bf16 hy = __float2bfloat16(y);
    __nv_bfloat162 H; H.x = hx; H.y = hy;
    __nv_bfloat162 L;
    L.x = __float2bfloat16(x - __bfloat162float(hx));
    L.y = __float2bfloat16(y - __bfloat162float(hy));
    h = *(uint32_t*)&H;
    l = *(uint32_t*)&L;
}

// ---------------------------------------------------------------------------
// fp32 -> (hi,lo) split into TILED layout
// ---------------------------------------------------------------------------
__global__ __launch_bounds__(256) void split_x_tiled(
    const float4* __restrict__ in, bf16* __restrict__ hi, bf16* __restrict__ lo, int n4)
{
    int i = blockIdx.x * blockDim.x + threadIdx.x;
    if (i >= n4) return;
    float4 v = in[i];
    const int row = i >> 8;
    const int c = (i & 255) * 4;
    const size_t off = tiled_off(row, c);
    uint32_t h0, l0, h1, l1;
    split2(v.x, v.y, h0, l0);
    split2(v.z, v.w, h1, l1);
    *(uint2*)(hi + off) = make_uint2(h0, h1);
    *(uint2*)(lo + off) = make_uint2(l0, l1);
}

__global__ __launch_bounds__(256) void split_w4_tiled(
    const float4* __restrict__ w0, const float4* __restrict__ w1,
    const float4* __restrict__ w2, const float4* __restrict__ w3,
    bf16* __restrict__ h0p, bf16* __restrict__ l0p,
    bf16* __restrict__ h1p, bf16* __restrict__ l1p,
    bf16* __restrict__ h2p, bf16* __restrict__ l2p,
    bf16* __restrict__ h3p, bf16* __restrict__ l3p, int wn4)
{
    int gid = blockIdx.x * blockDim.x + threadIdx.x;
    int sel = gid / wn4;
    int i = gid - sel * wn4;
    const float4* in; bf16 *hi, *lo;
    if (sel == 0)      { in = w0; hi = h0p; lo = l0p; }
    else if (sel == 1) { in = w1; hi = h1p; lo = l1p; }
    else if (sel == 2) { in = w2; hi = h2p; lo = l2p; }
    else               { in = w3; hi = h3p; lo = l3p; }
    float4 v = in[i];
    const int row = i >> 8;
    const int c = (i & 255) * 4;
    const size_t off = tiled_off(row, c);
    uint32_t a0, b0, a1, b1;
    split2(v.x, v.y, a0, b0);
    split2(v.z, v.w, a1, b1);
    *(uint2*)(hi + off) = make_uint2(a0, a1);
    *(uint2*)(lo + off) = make_uint2(b0, b1);
}

// ---------------------------------------------------------------------------
// bf16x3 GEMM: BM=256, BN=128, BK=32; 8 warps, warp tile 64x64; 3-stage bulk.
// EPI: 0 = fp32 C + bias; 1 = bias + split to linear hi/lo;
//      2 = bias + RMSNORM(head=warp's 64-col span) + scale + split to hi/lo.
// ---------------------------------------------------------------------------
#define NKT NKB
#define AST (6 * TBLK_BYTES)             // 61440 per stage
#define GEMM_SMEM (128 + 3 * AST)        // 184448

template <int EPI>
__device__ __forceinline__ void gemm_core(
    const bf16* __restrict__ Ah, const bf16* __restrict__ Al,
    const bf16* __restrict__ Bh, const bf16* __restrict__ Bl,
    const float* __restrict__ bias, float* __restrict__ C,
    bf16* __restrict__ Oh, bf16* __restrict__ Ol,
    const float* __restrict__ nw, float nscale, int M,
    int mblk, int nblk, char* dsm)
{
    const uint32_t sbase = smem_u32(dsm);
    const uint32_t tiles = sbase + 128;
    const int tid = threadIdx.x;
    const int wid = tid >> 5;
    const int lane = tid & 31;
    const int wm = wid & 3;
    const int wn = wid >> 2;

    float acc[4][8][4];
#pragma unroll
    for (int i = 0; i < 4; i++)
#pragma unroll
        for (int j = 0; j < 8; j++)
#pragma unroll
            for (int r = 0; r < 4; r++) acc[i][j][r] = 0.0f;

    if (tid == 0) {
        MBAR_INIT(sbase + 0, 1);
        MBAR_INIT(sbase + 8, 1);
        MBAR_INIT(sbase + 16, 1);
    }
    __syncthreads();

    const size_t a0_blk = (size_t)(mblk * 2) * NKB;
    const size_t a1_blk = (size_t)(mblk * 2 + 1) * NKB;
    const size_t b_blk  = (size_t)nblk * NKB;

    auto issue = [&](int kt) {
        const int s = kt - (kt / 3) * 3;
        const uint32_t dst = tiles + s * AST;
        const uint32_t m = sbase + s * 8;
        MBAR_EXPECT_TX(m, (uint32_t)AST);
        const size_t ao0 = (a0_blk + kt) * TBLK_ELEMS;
        const size_t ao1 = (a1_blk + kt) * TBLK_ELEMS;
        const size_t bo  = (b_blk + kt) * TBLK_ELEMS;
        BULK_G2S(dst + 0 * TBLK_BYTES, Ah + ao0, (uint32_t)TBLK_BYTES, m);
        BULK_G2S(dst + 1 * TBLK_BYTES, Ah + ao1, (uint32_t)TBLK_BYTES, m);
        BULK_G2S(dst + 2 * TBLK_BYTES, Al + ao0, (uint32_t)TBLK_BYTES, m);
        BULK_G2S(dst + 3 * TBLK_BYTES, Al + ao1, (uint32_t)TBLK_BYTES, m);
        BULK_G2S(dst + 4 * TBLK_BYTES, Bh + bo,  (uint32_t)TBLK_BYTES, m);
        BULK_G2S(dst + 5 * TBLK_BYTES, Bl + bo,  (uint32_t)TBLK_BYTES, m);
    };
    if (tid == 0) { issue(0); issue(1); issue(2); }

    const int a_row = (lane & 15);
    const int a_col = (lane >> 4) * 8;
    const int b_row = (lane & 7) + ((lane >> 4) & 1) * 8;
    const int b_col = ((lane >> 3) & 1) * 8;
    const int ablk = wm >> 1;
    const int arow0 = (wm & 1) * 64 + a_row;

    int phase[3] = {0, 0, 0};
    for (int kt = 0; kt < NKT; kt++) {
        const int s = kt - (kt / 3) * 3;
        mbar_wait(sbase + s * 8, phase[s]);
        phase[s] ^= 1;
        const uint32_t st = tiles + s * AST;

#pragma unroll
        for (int ph = 0; ph < 2; ph++) {
            const int koff = ph * 16;
            uint32_t af[2][4][4];
#pragma unroll
            for (int prod = 0; prod < 2; prod++) {
#pragma unroll
                for (int mf = 0; mf < 4; mf++) {
                    const uint32_t addr = st + (uint32_t)((prod * 2 + ablk) * TBLK_BYTES) +
                        (uint32_t)((arow0 + mf * 16) * (TROW * 2) + (koff + a_col) * 2);
                    LDSM_X4(af[prod][mf][0], af[prod][mf][1],
                            af[prod][mf][2], af[prod][mf][3], addr);
                }
            }
#pragma unroll
            for (int np = 0; np < 4; np++) {
                const uint32_t boff =
                    (uint32_t)((wn * 64 + np * 16 + b_row) * (TROW * 2) +
                               (koff + b_col) * 2);
                uint32_t bh[4], bl[4];
                LDSM_X4(bh[0], bh[1], bh[2], bh[3], st + 4 * TBLK_BYTES + boff);
                LDSM_X4(bl[0], bl[1], bl[2], bl[3], st + 5 * TBLK_BYTES + boff);
                uint32_t bh0[2] = {bh[0], bh[1]}, bh1[2] = {bh[2], bh[3]};
                uint32_t bl0[2] = {bl[0], bl[1]}, bl1[2] = {bl[2], bl[3]};
#pragma unroll
                for (int mf = 0; mf < 4; mf++) {
                    MMA16816(acc[mf][np * 2],     af[0][mf], bh0);
                    MMA16816(acc[mf][np * 2],     af[0][mf], bl0);
                    MMA16816(acc[mf][np * 2],     af[1][mf], bh0);
                    MMA16816(acc[mf][np * 2 + 1], af[0][mf], bh1);
                    MMA16816(acc[mf][np * 2 + 1], af[0][mf], bl1);
                    MMA16816(acc[mf][np * 2 + 1], af[1][mf], bh1);
                }
            }
        }
        __syncthreads();
        if (kt + 3 < NKT && tid == 0) issue(kt + 3);
    }

    const int m0 = mblk * 256, n0 = nblk * 128;
    const int rbase = m0 + wm * 64 + (lane >> 2);
    const int cbase = n0 + wn * 64 + (lane & 3) * 2;
#pragma unroll
    for (int mf = 0; mf < 4; mf++) {
#pragma unroll
        for (int half = 0; half < 2; half++) {
            const int row = rbase + mf * 16 + half * 8;
            if (row >= M) continue;
            float v[8][2];
#pragma unroll
            for (int nf = 0; nf < 8; nf++) {
                const int col = cbase + nf * 8;
                v[nf][0] = acc[mf][nf][half * 2 + 0] + bias[col];
                v[nf][1] = acc[mf][nf][half * 2 + 1] + bias[col + 1];
            }
            if (EPI == 0) {
#pragma unroll
                for (int nf = 0; nf < 8; nf++) {
                    float2 o; o.x = v[nf][0]; o.y = v[nf][1];
                    *(float2*)(C + (size_t)row * C_DIM + cbase + nf * 8) = o;
                }
            } else if (EPI == 1) {
#pragma unroll
                for (int nf = 0; nf < 8; nf++) {
                    uint32_t h, l;
                    split2(v[nf][0], v[nf][1], h, l);
                    *(uint32_t*)(Oh + (size_t)row * C_DIM + cbase + nf * 8) = h;
                    *(uint32_t*)(Ol + (size_t)row * C_DIM + cbase + nf * 8) = l;
                }
            } else {
                // rmsnorm over the warp's 64-col head span
                float ss = 0.0f;
#pragma unroll
                for (int nf = 0; nf < 8; nf++)
                    ss += v[nf][0] * v[nf][0] + v[nf][1] * v[nf][1];
                ss += __shfl_xor_sync(0xffffffffu, ss, 1);
                ss += __shfl_xor_sync(0xffffffffu, ss, 2);
                const float r = rsqrtf(ss * (1.0f / HD) + EPS_RMS) * nscale;
                const int d0 = (lane & 3) * 2;
#pragma unroll
                for (int nf = 0; nf < 8; nf++) {
                    const int d = nf * 8 + d0;
                    uint32_t h, l;
                    split2(v[nf][0] * r * nw[d], v[nf][1] * r * nw[d + 1], h, l);
                    *(uint32_t*)(Oh + (size_t)row * C_DIM + cbase + nf * 8) = h;
                    *(uint32_t*)(Ol + (size_t)row * C_DIM + cbase + nf * 8) = l;
                }
            }
        }
    }
}

__global__ __launch_bounds__(256, 1)
void gemm_qkv(const bf16* __restrict__ xh, const bf16* __restrict__ xl,
              const bf16* __restrict__ wqh, const bf16* __restrict__ wql,
              const float* __restrict__ bq,
              const bf16* __restrict__ wkh, const bf16* __restrict__ wkl,
              const float* __restrict__ bk,
              const bf16* __restrict__ wvh, const bf16* __restrict__ wvl,
              const float* __restrict__ bv,
              const float* __restrict__ qn, const float* __restrict__ kn,
              bf16* __restrict__ qh, bf16* __restrict__ ql,
              bf16* __restrict__ kh, bf16* __restrict__ kl,
              bf16* __restrict__ vh, bf16* __restrict__ vl, int M)
{
    extern __shared__ char dsm[];
    const int z = blockIdx.z;
    if (z == 0) {
        gemm_core<2>(xh, xl, wqh, wql, bq, nullptr, qh, ql, qn, 0.125f, M,
                     blockIdx.y, blockIdx.x, dsm);
    } else if (z == 1) {
        gemm_core<2>(xh, xl, wkh, wkl, bk, nullptr, kh, kl, kn, 1.0f, M,
                     blockIdx.y, blockIdx.x, dsm);
    } else {
        gemm_core<1>(xh, xl, wvh, wvl, bv, nullptr, vh, vl, nullptr, 0.f, M,
                     blockIdx.y, blockIdx.x, dsm);
    }
}

__global__ __launch_bounds__(256, 1)
void gemm_single(const bf16* __restrict__ Ah, const bf16* __restrict__ Al,
                 const bf16* __restrict__ Bh, const bf16* __restrict__ Bl,
                 const float* __restrict__ bias, float* __restrict__ C, int M)
{
    extern __shared__ char dsm[];
    gemm_core<0>(Ah, Al, Bh, Bl, bias, C, nullptr, nullptr, nullptr, 0.f, M,
                 blockIdx.y, blockIdx.x, dsm);
}

// ---------------------------------------------------------------------------
// Tensorized varlen attention (flash-2, bf16x3); epilogue writes TILED layout
// ---------------------------------------------------------------------------
#define KSTRIDE_B 144
#define ARR_B (64 * KSTRIDE_B)
#define ATT_STAGE (4 * ARR_B)
#define ATT_SMEM (2 * ATT_STAGE)

__global__ __launch_bounds__(256, 2) void attn_mma(const int* __restrict__ cu)
{
    const int seq = blockIdx.x;
    const int head = blockIdx.y;
    const int s0 = cu[seq];
    const int L = cu[seq + 1] - s0;
    const int q0 = blockIdx.z * 128;
    if (q0 >= L) return;

    extern __shared__ char sm[];
    const uint32_t sb = smem_u32(sm);
    const int tid = threadIdx.x;
    const int wid = tid >> 5;
    const int lane = tid & 31;
    const int colh = head * HD;

    uint32_t aQh[4][4], aQl[4][4];
    {
        int r0 = q0 + wid * 16 + (lane >> 2);
        int r1 = r0 + 8;
        if (r0 >= L) r0 = L - 1;
        if (r1 >= L) r1 = L - 1;
        const size_t b0 = (size_t)(s0 + r0) * C_DIM + colh + (lane & 3) * 2;
        const size_t b1 = (size_t)(s0 + r1) * C_DIM + colh + (lane & 3) * 2;
#pragma unroll
        for (int kc = 0; kc < 4; kc++) {
            aQh[kc][0] = *(const uint32_t*)(g_qh + b0 + kc * 16);
            aQh[kc][1] = *(const uint32_t*)(g_qh + b1 + kc * 16);
            aQh[kc][2] = *(const uint32_t*)(g_qh + b0 + kc * 16 + 8);
            aQh[kc][3] = *(const uint32_t*)(g_qh + b1 + kc * 16 + 8);
            aQl[kc][0] = *(const uint32_t*)(g_ql + b0 + kc * 16);
            aQl[kc][1] = *(const uint32_t*)(g_ql + b1 + kc * 16);
            aQl[kc][2] = *(const uint32_t*)(g_ql + b0 + kc * 16 + 8);
            aQl[kc][3] = *(const uint32_t*)(g_ql + b1 + kc * 16 + 8);
        }
    }

    float o[8][4];
#pragma unroll
    for (int i = 0; i < 8; i++)
#pragma unroll
        for (int j = 0; j < 4; j++) o[i][j] = 0.0f;
    float m0 = -1e30f, m1 = -1e30f, l0 = 0.0f, l1 = 0.0f;

    const int ntiles = (L + 63) >> 6;

    auto load_tile = [&](int t) {
        const uint32_t st = sb + (t & 1) * ATT_STAGE;
        const int kb = t * 64;
        const bf16* srcs[4] = {g_kh2, g_kl2, g_vh2, g_vl2};
#pragma unroll
        for (int i = 0; i < 8; i++) {
            int c = tid + i * 256;
            int arr = c >> 9;
            int r = (c >> 3) & 63;
            int cc = c & 7;
            int key = kb + r;
            if (key >= L) key = L - 1;
            const void* g = srcs[arr] + (size_t)(s0 + key) * C_DIM + colh + cc * 8;
            CP_ASYNC16(st + arr * ARR_B + r * KSTRIDE_B + cc * 16, g);
        }
    };

    load_tile(0);
    CP_COMMIT();

    for (int t = 0; t < ntiles; t++) {
        if (t + 1 < ntiles) { load_tile(t + 1); CP_COMMIT(); CP_WAIT(1); }
        else { CP_WAIT(0); }
        __syncthreads();
        const uint32_t st = sb + (t & 1) * ATT_STAGE;
        const int kb = t * 64;

        float s[8][4];
#pragma unroll
        for (int i = 0; i < 8; i++)
#pragma unroll
            for (int j = 0; j < 4; j++) s[i][j] = 0.0f;

        const int mat = lane >> 3;
#pragma unroll
        for (int kc = 0; kc < 4; kc++) {
#pragma unroll
            for (int pair = 0; pair < 4; pair++) {
                const int krow = (pair * 2 + (mat >> 1)) * 8 + (lane & 7);
                const uint32_t cb = (uint32_t)(kc * 32 + (mat & 1) * 16);
                uint32_t kh[4], kl[4];
                LDSM_X4(kh[0], kh[1], kh[2], kh[3], st + 0     + krow * KSTRIDE_B + cb);
                LDSM_X4(kl[0], kl[1], kl[2], kl[3], st + ARR_B + krow * KSTRIDE_B + cb);
                uint32_t bh0[2] = {kh[0], kh[1]}, bh1[2] = {kh[2], kh[3]};
                uint32_t bl0[2] = {kl[0], kl[1]}, bl1[2] = {kl[2], kl[3]};
                MMA16816(s[pair * 2],     aQh[kc], bh0);
                MMA16816(s[pair * 2],     aQh[kc], bl0);
                MMA16816(s[pair * 2],     aQl[kc], bh0);
                MMA16816(s[pair * 2 + 1], aQh[kc], bh1);
                MMA16816(s[pair * 2 + 1], aQh[kc], bl1);
                MMA16816(s[pair * 2 + 1], aQl[kc], bh1);
            }
        }

        const int cb0 = (lane & 3) * 2;
#pragma unroll
        for (int nf = 0; nf < 8; nf++) {
            int colk = kb + nf * 8 + cb0;
            if (colk >= L)     { s[nf][0] = -1e30f; s[nf][2] = -1e30f; }
            if (colk + 1 >= L) { s[nf][1] = -1e30f; s[nf][3] = -1e30f; }
        }

        float mx0 = -1e30f, mx1 = -1e30f;
#pragma unroll
        for (int nf = 0; nf < 8; nf++) {
            mx0 = fmaxf(mx0, fmaxf(s[nf][0], s[nf][1]));
            mx1 = fmaxf(mx1, fmaxf(s[nf][2], s[nf][3]));
        }
        mx0 = fmaxf(mx0, __shfl_xor_sync(0xffffffffu, mx0, 1));
        mx0 = fmaxf(mx0, __shfl_xor_sync(0xffffffffu, mx0, 2));
        mx1 = fmaxf(mx1, __shfl_xor_sync(0xffffffffu, mx1, 1));
        mx1 = fmaxf(mx1, __shfl_xor_sync(0xffffffffu, mx1, 2));
        const float nm0 = fmaxf(m0, mx0);
        const float nm1 = fmaxf(m1, mx1);
        const float corr0 = __expf(m0 - nm0);
        const float corr1 = __expf(m1 - nm1);
        m0 = nm0; m1 = nm1;
        l0 *= corr0; l1 *= corr1;
#pragma unroll
        for (int nf = 0; nf < 8; nf++) {
            o[nf][0] *= corr0; o[nf][1] *= corr0;
            o[nf][2] *= corr1; o[nf][3] *= corr1;
        }
#pragma unroll
        for (int nf = 0; nf < 8; nf++) {
            s[nf][0] = __expf(s[nf][0] - m0);
            s[nf][1] = __expf(s[nf][1] - m0);
            s[nf][2] = __expf(s[nf][2] - m1);
            s[nf][3] = __expf(s[nf][3] - m1);
            l0 += s[nf][0] + s[nf][1];
            l1 += s[nf][2] + s[nf][3];
        }

#pragma unroll
        for (int j = 0; j < 4; j++) {
            uint32_t ph[4], pl[4];
            split2(s[2 * j][0], s[2 * j][1], ph[0], pl[0]);
            split2(s[2 * j][2], s[2 * j][3], ph[1], pl[1]);
            split2(s[2 * j + 1][0], s[2 * j + 1][1], ph[2], pl[2]);
            split2(s[2 * j + 1][2], s[2 * j + 1][3], ph[3], pl[3]);
            const uint32_t vrow = (uint32_t)((j * 16 + (lane & 15)) * KSTRIDE_B +
                                             ((lane >> 4) << 3) * 2);
#pragma unroll
            for (int vp = 0; vp < 4; vp++) {
                const uint32_t addr = st + 2 * ARR_B + vrow + (uint32_t)(vp * 32);
                uint32_t vh[4], vl[4];
                LDSM_X4_T(vh[0], vh[1], vh[2], vh[3], addr);
                LDSM_X4_T(vl[0], vl[1], vl[2], vl[3], addr + ARR_B);
                uint32_t bh0[2] = {vh[0], vh[1]}, bh1[2] = {vh[2], vh[3]};
                uint32_t bl0[2] = {vl[0], vl[1]}, bl1[2] = {vl[2], vl[3]};
                MMA16816(o[vp * 2],     ph, bh0);
                MMA16816(o[vp * 2],     pl, bh0);
                MMA16816(o[vp * 2],     ph, bl0);
                MMA16816(o[vp * 2 + 1], ph, bh1);
                MMA16816(o[vp * 2 + 1], pl, bh1);
                MMA16816(o[vp * 2 + 1], ph, bl1);
            }
        }
        __syncthreads();
    }

    l0 += __shfl_xor_sync(0xffffffffu, l0, 1);
    l0 += __shfl_xor_sync(0xffffffffu, l0, 2);
    l1 += __shfl_xor_sync(0xffffffffu, l1, 1);
    l1 += __shfl_xor_sync(0xffffffffu, l1, 2);
    const float inv0 = 1.0f / l0;
    const float inv1 = 1.0f / l1;
    const int r0 = q0 + wid * 16 + (lane >> 2);
    const int r1 = r0 + 8;
#pragma unroll
    for (int nf = 0; nf < 8; nf++) {
        const int col = colh + nf * 8 + (lane & 3) * 2;
        if (r0 < L) {
            uint32_t h, l;
            split2(o[nf][0] * inv0, o[nf][1] * inv0, h, l);
            const size_t off = tiled_off(s0 + r0, col);
            *(uint32_t*)(g_ath + off) = h;
            *(uint32_t*)(g_atl + off) = l;
        }
        if (r1 < L) {
            uint32_t h, l;
            split2(o[nf][2] * inv1, o[nf][3] * inv1, h, l);
            const size_t off = tiled_off(s0 + r1, col);
            *(uint32_t*)(g_ath + off) = h;
            *(uint32_t*)(g_atl + off) = l;
        }
    }
}

// ---------------------------------------------------------------------------
// Launch
// ---------------------------------------------------------------------------
extern "C" void kernel_launch(void* const* d_in, const int* in_sizes, int n_in,
                              void* d_out, int out_size)
{
    const float* x  = (const float*)d_in[0];
    const int* cu   = (const int*)d_in[1];
    const float* Wq = (const float*)d_in[2];
    const float* bq = (const float*)d_in[3];
    const float* Wk = (const float*)d_in[4];
    const float* bk = (const float*)d_in[5];
    const float* Wv = (const float*)d_in[6];
    const float* bv = (const float*)d_in[7];
    const float* qn = (const float*)d_in[8];
    const float* kn = (const float*)d_in[9];
    const float* Wo = (const float*)d_in[10];
    const float* bo = (const float*)d_in[11];
    float* out = (float*)d_out;

    const int T = in_sizes[0] / C_DIM;
    const int nseq = in_sizes[1] - 1;

    bf16 *xh, *xl, *qh, *ql, *kh, *kl, *vh, *vl, *ath, *atl;
    bf16 *wqh, *wql, *wkh, *wkl, *wvh, *wvl, *woh, *wol;
    cudaGetSymbolAddress((void**)&xh, g_xh);
    cudaGetSymbolAddress((void**)&xl, g_xl);
    cudaGetSymbolAddress((void**)&qh, g_qh);
    cudaGetSymbolAddress((void**)&ql, g_ql);
    cudaGetSymbolAddress((void**)&kh, g_kh2);
    cudaGetSymbolAddress((void**)&kl, g_kl2);
    cudaGetSymbolAddress((void**)&vh, g_vh2);
    cudaGetSymbolAddress((void**)&vl, g_vl2);
    cudaGetSymbolAddress((void**)&ath, g_ath);
    cudaGetSymbolAddress((void**)&atl, g_atl);
    cudaGetSymbolAddress((void**)&wqh, g_wqh);
    cudaGetSymbolAddress((void**)&wql, g_wql);
    cudaGetSymbolAddress((void**)&wkh, g_wkh);
    cudaGetSymbolAddress((void**)&wkl, g_wkl);
    cudaGetSymbolAddress((void**)&wvh, g_wvh);
    cudaGetSymbolAddress((void**)&wvl, g_wvl);
    cudaGetSymbolAddress((void**)&woh, g_woh);
    cudaGetSymbolAddress((void**)&wol, g_wol);

    cudaFuncSetAttribute(gemm_qkv, cudaFuncAttributeMaxDynamicSharedMemorySize, GEMM_SMEM);
    cudaFuncSetAttribute(gemm_single, cudaFuncAttributeMaxDynamicSharedMemorySize, GEMM_SMEM);
    cudaFuncSetAttribute(attn_mma, cudaFuncAttributeMaxDynamicSharedMemorySize, ATT_SMEM);

    const int xn4 = T * C_DIM / 4;
    const int wn4 = C_DIM * C_DIM / 4;
    split_x_tiled<<<(xn4 + 255) / 256, 256>>>((const float4*)x, xh, xl, xn4);
    split_w4_tiled<<<(4 * wn4) / 256, 256>>>(
        (const float4*)Wq, (const float4*)Wk, (const float4*)Wv, (const float4*)Wo,
        wqh, wql, wkh, wkl, wvh, wvl, woh, wol, wn4);

    dim3 qkv_grid(C_DIM / 128, (T + 255) / 256, 3);
    gemm_qkv<<<qkv_grid, 256, GEMM_SMEM>>>(xh, xl,
                                           wqh, wql, bq,
                                           wkh, wkl, bk,
                                           wvh, wvl, bv,
                                           qn, kn,
                                           qh, ql, kh, kl, vh, vl, T);

    dim3 attn_grid(nseq, NH, LMAX / 128);
    attn_mma<<<attn_grid, 256, ATT_SMEM>>>(cu);

    dim3 ggrid(C_DIM / 128, (T + 255) / 256);
    gemm_single<<<ggrid, 256, GEMM_SMEM>>>(ath, atl, woh, wol, bo, out, T);
}

// round 9
// speedup vs baseline: 1.0889x; 1.0889x over previous
#include <cuda_runtime.h>
#include <cuda_bf16.h>
#include <cstdint>

#define C_DIM 1024
#define NH 16
#define HD 64
#define MAX_T 8192
#define LMAX 1024
#define EPS_RMS 1.1920929e-07f

typedef __nv_bfloat16 bf16;

// ---------------- scratch (device globals; allocation-free rule) ----------
// linear layouts (attention operands)
__device__ bf16 g_qh[MAX_T * C_DIM];
__device__ bf16 g_ql[MAX_T * C_DIM];
__device__ bf16 g_kh2[MAX_T * C_DIM];
__device__ bf16 g_kl2[MAX_T * C_DIM];
__device__ bf16 g_vh2[MAX_T * C_DIM];
__device__ bf16 g_vl2[MAX_T * C_DIM];

// tiled layouts (GEMM operands): [blk128][kblk32][128 rows x 40 elems]
#define TROW 40
#define TBLK_ELEMS (128 * TROW)       // 5120 elems
#define TBLK_BYTES (TBLK_ELEMS * 2)   // 10240 B
#define NKB (C_DIM / 32)              // 32 k-blocks
__device__ bf16 g_xh[(MAX_T / 128) * NKB * TBLK_ELEMS];
__device__ bf16 g_xl[(MAX_T / 128) * NKB * TBLK_ELEMS];
__device__ bf16 g_ath[(MAX_T / 128) * NKB * TBLK_ELEMS];
__device__ bf16 g_atl[(MAX_T / 128) * NKB * TBLK_ELEMS];
__device__ bf16 g_wqh[8 * NKB * TBLK_ELEMS];
__device__ bf16 g_wql[8 * NKB * TBLK_ELEMS];
__device__ bf16 g_wkh[8 * NKB * TBLK_ELEMS];
__device__ bf16 g_wkl[8 * NKB * TBLK_ELEMS];
__device__ bf16 g_wvh[8 * NKB * TBLK_ELEMS];
__device__ bf16 g_wvl[8 * NKB * TBLK_ELEMS];
__device__ bf16 g_woh[8 * NKB * TBLK_ELEMS];
__device__ bf16 g_wol[8 * NKB * TBLK_ELEMS];

// ---------------- helpers ---------------------------------------------
__device__ __forceinline__ uint32_t smem_u32(const void* p) {
    uint32_t a;
    asm("{ .reg .u64 t; cvta.to.shared.u64 t, %1; cvt.u32.u64 %0, t; }"
        : "=r"(a) : "l"(p));
    return a;
}

__device__ __forceinline__ size_t tiled_off(int r, int c) {
    return ((size_t)((r >> 7) * NKB + (c >> 5))) * TBLK_ELEMS +
           (size_t)((r & 127) * TROW + (c & 31));
}

#define LDSM_X4(r0, r1, r2, r3, addr) \
    asm volatile("ldmatrix.sync.aligned.m8n8.x4.shared.b16 {%0,%1,%2,%3}, [%4];" \
                 : "=r"(r0), "=r"(r1), "=r"(r2), "=r"(r3) : "r"(addr))

#define LDSM_X4_T(r0, r1, r2, r3, addr) \
    asm volatile("ldmatrix.sync.aligned.m8n8.x4.trans.shared.b16 {%0,%1,%2,%3}, [%4];" \
                 : "=r"(r0), "=r"(r1), "=r"(r2), "=r"(r3) : "r"(addr))

#define MMA16816(d, a, b) \
    asm volatile("mma.sync.aligned.m16n8k16.row.col.f32.bf16.bf16.f32 " \
                 "{%0,%1,%2,%3}, {%4,%5,%6,%7}, {%8,%9}, {%0,%1,%2,%3};" \
                 : "+f"((d)[0]), "+f"((d)[1]), "+f"((d)[2]), "+f"((d)[3]) \
                 : "r"((a)[0]), "r"((a)[1]), "r"((a)[2]), "r"((a)[3]), \
                   "r"((b)[0]), "r"((b)[1]))

#define CP_ASYNC16(dst, src) \
    asm volatile("cp.async.cg.shared.global [%0], [%1], 16;" :: "r"(dst), "l"(src))
#define CP_COMMIT() asm volatile("cp.async.commit_group;" ::: "memory")
#define CP_WAIT(n)  asm volatile("cp.async.wait_group %0;" :: "n"(n) : "memory")

#define MBAR_INIT(a, cnt) \
    asm volatile("mbarrier.init.shared.b64 [%0], %1;" :: "r"(a), "r"(cnt) : "memory")
#define MBAR_EXPECT_TX(a, bytes) \
    asm volatile("mbarrier.arrive.expect_tx.shared.b64 _, [%0], %1;" \
                 :: "r"(a), "r"(bytes) : "memory")
#define BULK_G2S(dst, src, bytes, mbar) \
    asm volatile("cp.async.bulk.shared::cta.global.mbarrier::complete_tx::bytes " \
                 "[%0], [%1], %2, [%3];" \
                 :: "r"(dst), "l"(src), "r"(bytes), "r"(mbar) : "memory")

__device__ __forceinline__ void mbar_wait(uint32_t a, int phase) {
    asm volatile(
        "{ .reg .pred P;\n"
        "WL%=:\n"
        " mbarrier.try_wait.parity.acquire.cta.shared::cta.b64 P, [%0], %1, 0x989680;\n"
        " @P bra WD%=;\n"
        " bra WL%=;\n"
        "WD%=: }"
        :: "r"(a), "r"(phase) : "memory");
}

__device__ __forceinline__ void split2(float x, float y, uint32_t& h, uint32_t& l) {
    bf16 hx = __float2bfloat16(x);
    bf16 hy = __float2bfloat16(y);
    __nv_bfloat162 H; H.x = hx; H.y = hy;
    __nv_bfloat162 L;
    L.x = __float2bfloat16(x - __bfloat162float(hx));
    L.y = __float2bfloat16(y - __bfloat162float(hy));
    h = *(uint32_t*)&H;
    l = *(uint32_t*)&L;
}

// ---------------------------------------------------------------------------
// fp32 -> (hi,lo) split into TILED layout
// ---------------------------------------------------------------------------
__global__ __launch_bounds__(256) void split_x_tiled(
    const float4* __restrict__ in, bf16* __restrict__ hi, bf16* __restrict__ lo, int n4)
{
    int i = blockIdx.x * blockDim.x + threadIdx.x;
    if (i >= n4) return;
    float4 v = in[i];
    const int row = i >> 8;
    const int c = (i & 255) * 4;
    const size_t off = tiled_off(row, c);
    uint32_t h0, l0, h1, l1;
    split2(v.x, v.y, h0, l0);
    split2(v.z, v.w, h1, l1);
    *(uint2*)(hi + off) = make_uint2(h0, h1);
    *(uint2*)(lo + off) = make_uint2(l0, l1);
}

__global__ __launch_bounds__(256) void split_w4_tiled(
    const float4* __restrict__ w0, const float4* __restrict__ w1,
    const float4* __restrict__ w2, const float4* __restrict__ w3,
    bf16* __restrict__ h0p, bf16* __restrict__ l0p,
    bf16* __restrict__ h1p, bf16* __restrict__ l1p,
    bf16* __restrict__ h2p, bf16* __restrict__ l2p,
    bf16* __restrict__ h3p, bf16* __restrict__ l3p, int wn4)
{
    int gid = blockIdx.x * blockDim.x + threadIdx.x;
    int sel = gid / wn4;
    int i = gid - sel * wn4;
    const float4* in; bf16 *hi, *lo;
    if (sel == 0)      { in = w0; hi = h0p; lo = l0p; }
    else if (sel == 1) { in = w1; hi = h1p; lo = l1p; }
    else if (sel == 2) { in = w2; hi = h2p; lo = l2p; }
    else               { in = w3; hi = h3p; lo = l3p; }
    float4 v = in[i];
    const int row = i >> 8;
    const int c = (i & 255) * 4;
    const size_t off = tiled_off(row, c);
    uint32_t a0, b0, a1, b1;
    split2(v.x, v.y, a0, b0);
    split2(v.z, v.w, a1, b1);
    *(uint2*)(hi + off) = make_uint2(a0, a1);
    *(uint2*)(lo + off) = make_uint2(b0, b1);
}

// ---------------------------------------------------------------------------
// bf16x3 GEMM: BM=128, BN=128, BK=32; 8 warps (4x2), warp tile 32x64;
// 2-stage bulk-copy double buffer; occupancy 2.
// EPI: 0 = fp32 C + bias; 1 = bias + split to linear hi/lo;
//      2 = bias + RMSNORM(warp's 64-col head span) + scale + split to hi/lo.
// ---------------------------------------------------------------------------
#define NKT NKB
#define SUBTILE_B TBLK_BYTES              // 10240
#define STAGE_BYTES (4 * SUBTILE_B)       // 40960 (Ah, Al, Bh, Bl)
#define GEMM_SMEM (128 + 2 * STAGE_BYTES) // 82048

template <int EPI>
__device__ __forceinline__ void gemm_core(
    const bf16* __restrict__ Ah, const bf16* __restrict__ Al,
    const bf16* __restrict__ Bh, const bf16* __restrict__ Bl,
    const float* __restrict__ bias, float* __restrict__ C,
    bf16* __restrict__ Oh, bf16* __restrict__ Ol,
    const float* __restrict__ nw, float nscale, int M,
    int mblk, int nblk, char* dsm)
{
    const uint32_t sbase = smem_u32(dsm);
    const uint32_t mb0 = sbase, mb1 = sbase + 8;
    const uint32_t tiles = sbase + 128;
    const int tid = threadIdx.x;
    const int wid = tid >> 5;
    const int lane = tid & 31;
    const int wm = wid & 3;
    const int wn = wid >> 2;

    float acc[2][8][4];
#pragma unroll
    for (int i = 0; i < 2; i++)
#pragma unroll
        for (int j = 0; j < 8; j++)
#pragma unroll
            for (int r = 0; r < 4; r++) acc[i][j][r] = 0.0f;

    if (tid == 0) { MBAR_INIT(mb0, 1); MBAR_INIT(mb1, 1); }
    __syncthreads();

    const size_t abase_blk = (size_t)mblk * NKB;
    const size_t bbase_blk = (size_t)nblk * NKB;

    auto issue = [&](int kt) {
        const int s = kt & 1;
        const uint32_t dst = tiles + s * STAGE_BYTES;
        const uint32_t m = s ? mb1 : mb0;
        MBAR_EXPECT_TX(m, (uint32_t)STAGE_BYTES);
        const size_t ao = (abase_blk + kt) * TBLK_ELEMS;
        const size_t bo = (bbase_blk + kt) * TBLK_ELEMS;
        BULK_G2S(dst,                  Ah + ao, (uint32_t)TBLK_BYTES, m);
        BULK_G2S(dst + SUBTILE_B,      Al + ao, (uint32_t)TBLK_BYTES, m);
        BULK_G2S(dst + 2 * SUBTILE_B,  Bh + bo, (uint32_t)TBLK_BYTES, m);
        BULK_G2S(dst + 3 * SUBTILE_B,  Bl + bo, (uint32_t)TBLK_BYTES, m);
    };
    if (tid == 0) { issue(0); issue(1); }

    const int a_row = (lane & 15);
    const int a_col = (lane >> 4) * 8;
    const int b_row = (lane & 7) + ((lane >> 4) & 1) * 8;
    const int b_col = ((lane >> 3) & 1) * 8;

    int ph0 = 0, ph1 = 0;
    for (int kt = 0; kt < NKT; kt++) {
        const int s = kt & 1;
        if (s == 0) { mbar_wait(mb0, ph0); ph0 ^= 1; }
        else        { mbar_wait(mb1, ph1); ph1 ^= 1; }
        const uint32_t st = tiles + s * STAGE_BYTES;

#pragma unroll
        for (int ph = 0; ph < 2; ph++) {
            const int koff = ph * 16;
            uint32_t af[2][2][4];
#pragma unroll
            for (int prod = 0; prod < 2; prod++) {
                const uint32_t abase = st + prod * SUBTILE_B;
#pragma unroll
                for (int mf = 0; mf < 2; mf++) {
                    const uint32_t addr = abase +
                        (uint32_t)((wm * 32 + mf * 16 + a_row) * (TROW * 2) +
                                   (koff + a_col) * 2);
                    LDSM_X4(af[prod][mf][0], af[prod][mf][1],
                            af[prod][mf][2], af[prod][mf][3], addr);
                }
            }
#pragma unroll
            for (int np = 0; np < 4; np++) {
                const uint32_t boff =
                    (uint32_t)((wn * 64 + np * 16 + b_row) * (TROW * 2) +
                               (koff + b_col) * 2);
                uint32_t bh[4], bl[4];
                LDSM_X4(bh[0], bh[1], bh[2], bh[3], st + 2 * SUBTILE_B + boff);
                LDSM_X4(bl[0], bl[1], bl[2], bl[3], st + 3 * SUBTILE_B + boff);
                uint32_t bh0[2] = {bh[0], bh[1]}, bh1[2] = {bh[2], bh[3]};
                uint32_t bl0[2] = {bl[0], bl[1]}, bl1[2] = {bl[2], bl[3]};
#pragma unroll
                for (int mf = 0; mf < 2; mf++) {
                    MMA16816(acc[mf][np * 2],     af[0][mf], bh0);
                    MMA16816(acc[mf][np * 2],     af[0][mf], bl0);
                    MMA16816(acc[mf][np * 2],     af[1][mf], bh0);
                    MMA16816(acc[mf][np * 2 + 1], af[0][mf], bh1);
                    MMA16816(acc[mf][np * 2 + 1], af[0][mf], bl1);
                    MMA16816(acc[mf][np * 2 + 1], af[1][mf], bh1);
                }
            }
        }
        __syncthreads();
        if (kt + 2 < NKT && tid == 0) issue(kt + 2);
    }

    const int m0 = mblk * 128, n0 = nblk * 128;
    const int rbase = m0 + wm * 32 + (lane >> 2);
    const int cbase = n0 + wn * 64 + (lane & 3) * 2;
#pragma unroll
    for (int mf = 0; mf < 2; mf++) {
#pragma unroll
        for (int half = 0; half < 2; half++) {
            const int row = rbase + mf * 16 + half * 8;
            if (row >= M) continue;
            float v[8][2];
#pragma unroll
            for (int nf = 0; nf < 8; nf++) {
                const int col = cbase + nf * 8;
                v[nf][0] = acc[mf][nf][half * 2 + 0] + bias[col];
                v[nf][1] = acc[mf][nf][half * 2 + 1] + bias[col + 1];
            }
            if (EPI == 0) {
#pragma unroll
                for (int nf = 0; nf < 8; nf++) {
                    float2 o; o.x = v[nf][0]; o.y = v[nf][1];
                    *(float2*)(C + (size_t)row * C_DIM + cbase + nf * 8) = o;
                }
            } else if (EPI == 1) {
#pragma unroll
                for (int nf = 0; nf < 8; nf++) {
                    uint32_t h, l;
                    split2(v[nf][0], v[nf][1], h, l);
                    *(uint32_t*)(Oh + (size_t)row * C_DIM + cbase + nf * 8) = h;
                    *(uint32_t*)(Ol + (size_t)row * C_DIM + cbase + nf * 8) = l;
                }
            } else {
                // rmsnorm over the warp's 64-col head span (4 lanes x 16 vals)
                float ss = 0.0f;
#pragma unroll
                for (int nf = 0; nf < 8; nf++)
                    ss += v[nf][0] * v[nf][0] + v[nf][1] * v[nf][1];
                ss += __shfl_xor_sync(0xffffffffu, ss, 1);
                ss += __shfl_xor_sync(0xffffffffu, ss, 2);
                const float r = rsqrtf(ss * (1.0f / HD) + EPS_RMS) * nscale;
                const int d0 = (lane & 3) * 2;
#pragma unroll
                for (int nf = 0; nf < 8; nf++) {
                    const int d = nf * 8 + d0;
                    uint32_t h, l;
                    split2(v[nf][0] * r * nw[d], v[nf][1] * r * nw[d + 1], h, l);
                    *(uint32_t*)(Oh + (size_t)row * C_DIM + cbase + nf * 8) = h;
                    *(uint32_t*)(Ol + (size_t)row * C_DIM + cbase + nf * 8) = l;
                }
            }
        }
    }
}

__global__ __launch_bounds__(256, 2)
void gemm_qkv(const bf16* __restrict__ xh, const bf16* __restrict__ xl,
              const bf16* __restrict__ wqh, const bf16* __restrict__ wql,
              const float* __restrict__ bq,
              const bf16* __restrict__ wkh, const bf16* __restrict__ wkl,
              const float* __restrict__ bk,
              const bf16* __restrict__ wvh, const bf16* __restrict__ wvl,
              const float* __restrict__ bv,
              const float* __restrict__ qn, const float* __restrict__ kn,
              bf16* __restrict__ qh, bf16* __restrict__ ql,
              bf16* __restrict__ kh, bf16* __restrict__ kl,
              bf16* __restrict__ vh, bf16* __restrict__ vl, int M)
{
    extern __shared__ char dsm[];
    const int z = blockIdx.z;
    if (z == 0) {
        gemm_core<2>(xh, xl, wqh, wql, bq, nullptr, qh, ql, qn, 0.125f, M,
                     blockIdx.y, blockIdx.x, dsm);
    } else if (z == 1) {
        gemm_core<2>(xh, xl, wkh, wkl, bk, nullptr, kh, kl, kn, 1.0f, M,
                     blockIdx.y, blockIdx.x, dsm);
    } else {
        gemm_core<1>(xh, xl, wvh, wvl, bv, nullptr, vh, vl, nullptr, 0.f, M,
                     blockIdx.y, blockIdx.x, dsm);
    }
}

__global__ __launch_bounds__(256, 2)
void gemm_single(const bf16* __restrict__ Ah, const bf16* __restrict__ Al,
                 const bf16* __restrict__ Bh, const bf16* __restrict__ Bl,
                 const float* __restrict__ bias, float* __restrict__ C, int M)
{
    extern __shared__ char dsm[];
    gemm_core<0>(Ah, Al, Bh, Bl, bias, C, nullptr, nullptr, nullptr, 0.f, M,
                 blockIdx.y, blockIdx.x, dsm);
}

// ---------------------------------------------------------------------------
// Tensorized varlen attention (flash-2, bf16x3); epilogue writes TILED layout
// ---------------------------------------------------------------------------
#define KSTRIDE_B 144
#define ARR_B (64 * KSTRIDE_B)
#define ATT_STAGE (4 * ARR_B)
#define ATT_SMEM (2 * ATT_STAGE)

__global__ __launch_bounds__(256, 2) void attn_mma(const int* __restrict__ cu)
{
    const int seq = blockIdx.x;
    const int head = blockIdx.y;
    const int s0 = cu[seq];
    const int L = cu[seq + 1] - s0;
    const int q0 = blockIdx.z * 128;
    if (q0 >= L) return;

    extern __shared__ char sm[];
    const uint32_t sb = smem_u32(sm);
    const int tid = threadIdx.x;
    const int wid = tid >> 5;
    const int lane = tid & 31;
    const int colh = head * HD;

    uint32_t aQh[4][4], aQl[4][4];
    {
        int r0 = q0 + wid * 16 + (lane >> 2);
        int r1 = r0 + 8;
        if (r0 >= L) r0 = L - 1;
        if (r1 >= L) r1 = L - 1;
        const size_t b0 = (size_t)(s0 + r0) * C_DIM + colh + (lane & 3) * 2;
        const size_t b1 = (size_t)(s0 + r1) * C_DIM + colh + (lane & 3) * 2;
#pragma unroll
        for (int kc = 0; kc < 4; kc++) {
            aQh[kc][0] = *(const uint32_t*)(g_qh + b0 + kc * 16);
            aQh[kc][1] = *(const uint32_t*)(g_qh + b1 + kc * 16);
            aQh[kc][2] = *(const uint32_t*)(g_qh + b0 + kc * 16 + 8);
            aQh[kc][3] = *(const uint32_t*)(g_qh + b1 + kc * 16 + 8);
            aQl[kc][0] = *(const uint32_t*)(g_ql + b0 + kc * 16);
            aQl[kc][1] = *(const uint32_t*)(g_ql + b1 + kc * 16);
            aQl[kc][2] = *(const uint32_t*)(g_ql + b0 + kc * 16 + 8);
            aQl[kc][3] = *(const uint32_t*)(g_ql + b1 + kc * 16 + 8);
        }
    }

    float o[8][4];
#pragma unroll
    for (int i = 0; i < 8; i++)
#pragma unroll
        for (int j = 0; j < 4; j++) o[i][j] = 0.0f;
    float m0 = -1e30f, m1 = -1e30f, l0 = 0.0f, l1 = 0.0f;

    const int ntiles = (L + 63) >> 6;

    auto load_tile = [&](int t) {
        const uint32_t st = sb + (t & 1) * ATT_STAGE;
        const int kb = t * 64;
        const bf16* srcs[4] = {g_kh2, g_kl2, g_vh2, g_vl2};
#pragma unroll
        for (int i = 0; i < 8; i++) {
            int c = tid + i * 256;
            int arr = c >> 9;
            int r = (c >> 3) & 63;
            int cc = c & 7;
            int key = kb + r;
            if (key >= L) key = L - 1;
            const void* g = srcs[arr] + (size_t)(s0 + key) * C_DIM + colh + cc * 8;
            CP_ASYNC16(st + arr * ARR_B + r * KSTRIDE_B + cc * 16, g);
        }
    };

    load_tile(0);
    CP_COMMIT();

    for (int t = 0; t < ntiles; t++) {
        if (t + 1 < ntiles) { load_tile(t + 1); CP_COMMIT(); CP_WAIT(1); }
        else { CP_WAIT(0); }
        __syncthreads();
        const uint32_t st = sb + (t & 1) * ATT_STAGE;
        const int kb = t * 64;

        float s[8][4];
#pragma unroll
        for (int i = 0; i < 8; i++)
#pragma unroll
            for (int j = 0; j < 4; j++) s[i][j] = 0.0f;

        const int mat = lane >> 3;
#pragma unroll
        for (int kc = 0; kc < 4; kc++) {
#pragma unroll
            for (int pair = 0; pair < 4; pair++) {
                const int krow = (pair * 2 + (mat >> 1)) * 8 + (lane & 7);
                const uint32_t cb = (uint32_t)(kc * 32 + (mat & 1) * 16);
                uint32_t kh[4], kl[4];
                LDSM_X4(kh[0], kh[1], kh[2], kh[3], st + 0     + krow * KSTRIDE_B + cb);
                LDSM_X4(kl[0], kl[1], kl[2], kl[3], st + ARR_B + krow * KSTRIDE_B + cb);
                uint32_t bh0[2] = {kh[0], kh[1]}, bh1[2] = {kh[2], kh[3]};
                uint32_t bl0[2] = {kl[0], kl[1]}, bl1[2] = {kl[2], kl[3]};
                MMA16816(s[pair * 2],     aQh[kc], bh0);
                MMA16816(s[pair * 2],     aQh[kc], bl0);
                MMA16816(s[pair * 2],     aQl[kc], bh0);
                MMA16816(s[pair * 2 + 1], aQh[kc], bh1);
                MMA16816(s[pair * 2 + 1], aQh[kc], bl1);
                MMA16816(s[pair * 2 + 1], aQl[kc], bh1);
            }
        }

        const int cb0 = (lane & 3) * 2;
#pragma unroll
        for (int nf = 0; nf < 8; nf++) {
            int colk = kb + nf * 8 + cb0;
            if (colk >= L)     { s[nf][0] = -1e30f; s[nf][2] = -1e30f; }
            if (colk + 1 >= L) { s[nf][1] = -1e30f; s[nf][3] = -1e30f; }
        }

        float mx0 = -1e30f, mx1 = -1e30f;
#pragma unroll
        for (int nf = 0; nf < 8; nf++) {
            mx0 = fmaxf(mx0, fmaxf(s[nf][0], s[nf][1]));
            mx1 = fmaxf(mx1, fmaxf(s[nf][2], s[nf][3]));
        }
        mx0 = fmaxf(mx0, __shfl_xor_sync(0xffffffffu, mx0, 1));
        mx0 = fmaxf(mx0, __shfl_xor_sync(0xffffffffu, mx0, 2));
        mx1 = fmaxf(mx1, __shfl_xor_sync(0xffffffffu, mx1, 1));
        mx1 = fmaxf(mx1, __shfl_xor_sync(0xffffffffu, mx1, 2));
        const float nm0 = fmaxf(m0, mx0);
        const float nm1 = fmaxf(m1, mx1);
        const float corr0 = __expf(m0 - nm0);
        const float corr1 = __expf(m1 - nm1);
        m0 = nm0; m1 = nm1;
        l0 *= corr0; l1 *= corr1;
#pragma unroll
        for (int nf = 0; nf < 8; nf++) {
            o[nf][0] *= corr0; o[nf][1] *= corr0;
            o[nf][2] *= corr1; o[nf][3] *= corr1;
        }
#pragma unroll
        for (int nf = 0; nf < 8; nf++) {
            s[nf][0] = __expf(s[nf][0] - m0);
            s[nf][1] = __expf(s[nf][1] - m0);
            s[nf][2] = __expf(s[nf][2] - m1);
            s[nf][3] = __expf(s[nf][3] - m1);
            l0 += s[nf][0] + s[nf][1];
            l1 += s[nf][2] + s[nf][3];
        }

#pragma unroll
        for (int j = 0; j < 4; j++) {
            uint32_t ph[4], pl[4];
            split2(s[2 * j][0], s[2 * j][1], ph[0], pl[0]);
            split2(s[2 * j][2], s[2 * j][3], ph[1], pl[1]);
            split2(s[2 * j + 1][0], s[2 * j + 1][1], ph[2], pl[2]);
            split2(s[2 * j + 1][2], s[2 * j + 1][3], ph[3], pl[3]);
            const uint32_t vrow = (uint32_t)((j * 16 + (lane & 15)) * KSTRIDE_B +
                                             ((lane >> 4) << 3) * 2);
#pragma unroll
            for (int vp = 0; vp < 4; vp++) {
                const uint32_t addr = st + 2 * ARR_B + vrow + (uint32_t)(vp * 32);
                uint32_t vh[4], vl[4];
                LDSM_X4_T(vh[0], vh[1], vh[2], vh[3], addr);
                LDSM_X4_T(vl[0], vl[1], vl[2], vl[3], addr + ARR_B);
                uint32_t bh0[2] = {vh[0], vh[1]}, bh1[2] = {vh[2], vh[3]};
                uint32_t bl0[2] = {vl[0], vl[1]}, bl1[2] = {vl[2], vl[3]};
                MMA16816(o[vp * 2],     ph, bh0);
                MMA16816(o[vp * 2],     pl, bh0);
                MMA16816(o[vp * 2],     ph, bl0);
                MMA16816(o[vp * 2 + 1], ph, bh1);
                MMA16816(o[vp * 2 + 1], pl, bh1);
                MMA16816(o[vp * 2 + 1], ph, bl1);
            }
        }
        __syncthreads();
    }

    l0 += __shfl_xor_sync(0xffffffffu, l0, 1);
    l0 += __shfl_xor_sync(0xffffffffu, l0, 2);
    l1 += __shfl_xor_sync(0xffffffffu, l1, 1);
    l1 += __shfl_xor_sync(0xffffffffu, l1, 2);
    const float inv0 = 1.0f / l0;
    const float inv1 = 1.0f / l1;
    const int r0 = q0 + wid * 16 + (lane >> 2);
    const int r1 = r0 + 8;
#pragma unroll
    for (int nf = 0; nf < 8; nf++) {
        const int col = colh + nf * 8 + (lane & 3) * 2;
        if (r0 < L) {
            uint32_t h, l;
            split2(o[nf][0] * inv0, o[nf][1] * inv0, h, l);
            const size_t off = tiled_off(s0 + r0, col);
            *(uint32_t*)(g_ath + off) = h;
            *(uint32_t*)(g_atl + off) = l;
        }
        if (r1 < L) {
            uint32_t h, l;
            split2(o[nf][2] * inv1, o[nf][3] * inv1, h, l);
            const size_t off = tiled_off(s0 + r1, col);
            *(uint32_t*)(g_ath + off) = h;
            *(uint32_t*)(g_atl + off) = l;
        }
    }
}

// ---------------------------------------------------------------------------
// Launch
// ---------------------------------------------------------------------------
extern "C" void kernel_launch(void* const* d_in, const int* in_sizes, int n_in,
                              void* d_out, int out_size)
{
    const float* x  = (const float*)d_in[0];
    const int* cu   = (const int*)d_in[1];
    const float* Wq = (const float*)d_in[2];
    const float* bq = (const float*)d_in[3];
    const float* Wk = (const float*)d_in[4];
    const float* bk = (const float*)d_in[5];
    const float* Wv = (const float*)d_in[6];
    const float* bv = (const float*)d_in[7];
    const float* qn = (const float*)d_in[8];
    const float* kn = (const float*)d_in[9];
    const float* Wo = (const float*)d_in[10];
    const float* bo = (const float*)d_in[11];
    float* out = (float*)d_out;

    const int T = in_sizes[0] / C_DIM;
    const int nseq = in_sizes[1] - 1;

    bf16 *xh, *xl, *qh, *ql, *kh, *kl, *vh, *vl, *ath, *atl;
    bf16 *wqh, *wql, *wkh, *wkl, *wvh, *wvl, *woh, *wol;
    cudaGetSymbolAddress((void**)&xh, g_xh);
    cudaGetSymbolAddress((void**)&xl, g_xl);
    cudaGetSymbolAddress((void**)&qh, g_qh);
    cudaGetSymbolAddress((void**)&ql, g_ql);
    cudaGetSymbolAddress((void**)&kh, g_kh2);
    cudaGetSymbolAddress((void**)&kl, g_kl2);
    cudaGetSymbolAddress((void**)&vh, g_vh2);
    cudaGetSymbolAddress((void**)&vl, g_vl2);
    cudaGetSymbolAddress((void**)&ath, g_ath);
    cudaGetSymbolAddress((void**)&atl, g_atl);
    cudaGetSymbolAddress((void**)&wqh, g_wqh);
    cudaGetSymbolAddress((void**)&wql, g_wql);
    cudaGetSymbolAddress((void**)&wkh, g_wkh);
    cudaGetSymbolAddress((void**)&wkl, g_wkl);
    cudaGetSymbolAddress((void**)&wvh, g_wvh);
    cudaGetSymbolAddress((void**)&wvl, g_wvl);
    cudaGetSymbolAddress((void**)&woh, g_woh);
    cudaGetSymbolAddress((void**)&wol, g_wol);

    cudaFuncSetAttribute(gemm_qkv, cudaFuncAttributeMaxDynamicSharedMemorySize, GEMM_SMEM);
    cudaFuncSetAttribute(gemm_single, cudaFuncAttributeMaxDynamicSharedMemorySize, GEMM_SMEM);
    cudaFuncSetAttribute(attn_mma, cudaFuncAttributeMaxDynamicSharedMemorySize, ATT_SMEM);

    const int xn4 = T * C_DIM / 4;
    const int wn4 = C_DIM * C_DIM / 4;
    split_x_tiled<<<(xn4 + 255) / 256, 256>>>((const float4*)x, xh, xl, xn4);
    split_w4_tiled<<<(4 * wn4) / 256, 256>>>(
        (const float4*)Wq, (const float4*)Wk, (const float4*)Wv, (const float4*)Wo,
        wqh, wql, wkh, wkl, wvh, wvl, woh, wol, wn4);

    dim3 qkv_grid(C_DIM / 128, (T + 127) / 128, 3);
    gemm_qkv<<<qkv_grid, 256, GEMM_SMEM>>>(xh, xl,
                                           wqh, wql, bq,
                                           wkh, wkl, bk,
                                           wvh, wvl, bv,
                                           qn, kn,
                                           qh, ql, kh, kl, vh, vl, T);

    dim3 attn_grid(nseq, NH, LMAX / 128);
    attn_mma<<<attn_grid, 256, ATT_SMEM>>>(cu);

    dim3 ggrid(C_DIM / 128, (T + 127) / 128);
    gemm_single<<<ggrid, 256, GEMM_SMEM>>>(ath, atl, woh, wol, bo, out, T);
}